// round 2
// baseline (speedup 1.0000x reference)
#include <cuda_runtime.h>
#include <stdint.h>

#define DIM        3200
#define HID        6400
#define NTOK       16384   // 8 * 2048
#define NEW_START  32000

// ---------------- scratch (static device globals; no allocation) ----------------
__device__ int   g_count;
__device__ int   g_tok[NTOK];
__device__ float g_H[(size_t)NTOK * HID];   // worst-case hidden activations

// ---------------- kernel 0: reset counter ----------------
__global__ void k_reset() { g_count = 0; }

// ---------------- kernel 1: compact masked token indices ----------------
__global__ void k_compact(const int* __restrict__ ids) {
    int t = blockIdx.x * blockDim.x + threadIdx.x;
    if (t < NTOK && ids[t] >= NEW_START) {
        int p = atomicAdd(&g_count, 1);
        g_tok[p] = t;
    }
}

// ---------------- kernel 2: embedding copy (all tokens) ----------------
// one block per token, float4 vectorized copy of 3200 floats (800 float4)
__global__ void k_copy(const float* __restrict__ emb,
                       const int*   __restrict__ ids,
                       float*       __restrict__ out) {
    int t = blockIdx.x;
    const float4* src = (const float4*)(emb + (size_t)ids[t] * DIM);
    float4*       dst = (float4*)(out + (size_t)t * DIM);
    #pragma unroll 4
    for (int i = threadIdx.x; i < DIM / 4; i += blockDim.x)
        dst[i] = src[i];
}

// ---------------- tiled fp32 GEMM over masked rows ----------------
// C[m, n] = act( sum_k A[m,k] * B[k,n] + bias[n] )  for m in [0, g_count)
// GATHER_A=1: A row m is Asrc[g_tok[m]]        (gathered embedding, lda = DIM)
// GATHER_A=0: A row m is g_H[m]                (lda = HID)
// SCATTER_C=1: C row m is out[g_tok[m]]        (ldc = DIM)
// SCATTER_C=0: C row m is g_H[m]               (ldc = HID)
#define BM 64
#define BN 64
#define BK 16
#define TM 4
#define TN 4

template<int RELU, int GATHER_A, int SCATTER_C>
__global__ void k_gemm(const float* __restrict__ A,   // used when GATHER_A==1 (out buffer: gathered embeddings)
                       const float* __restrict__ B,   // weights [K, N] row-major
                       const float* __restrict__ bias,
                       float*       __restrict__ C,   // used when SCATTER_C==1 (d_out)
                       int N, int K, int lda, int ldc) {
    __shared__ float As[BK][BM + 1];
    __shared__ float Bs[BK][BN];

    const int count = g_count;
    const int m0 = blockIdx.y * BM;
    if (m0 >= count) return;
    const int n0 = blockIdx.x * BN;

    const int tid = threadIdx.x;            // 256 threads
    const int tx = tid & 15;                 // 16
    const int ty = tid >> 4;                 // 16

    // A-load assignment: each thread loads a float4 (4 k-values) of one row
    const int a_mi = tid >> 2;               // 0..63  row within tile
    const int a_k  = (tid & 3) * 4;          // 0,4,8,12
    const int a_m  = m0 + a_mi;
    const float* arow = nullptr;
    if (a_m < count) {
        if (GATHER_A) arow = A + (size_t)g_tok[a_m] * lda;   // row = gathered emb at position g_tok[m]
        else          arow = g_H + (size_t)a_m * lda;
    }

    // B-load assignment: each thread loads a float4 of one k-row
    const int b_kb = tid >> 4;               // 0..15
    const int b_n  = (tid & 15) * 4;         // 0..60

    float acc[TM][TN];
    #pragma unroll
    for (int i = 0; i < TM; i++)
        #pragma unroll
        for (int j = 0; j < TN; j++) acc[i][j] = 0.0f;

    for (int k0 = 0; k0 < K; k0 += BK) {
        // load A tile (transposed into As[k][m])
        float4 va = make_float4(0.f, 0.f, 0.f, 0.f);
        if (arow) va = *(const float4*)(arow + k0 + a_k);
        As[a_k + 0][a_mi] = va.x;
        As[a_k + 1][a_mi] = va.y;
        As[a_k + 2][a_mi] = va.z;
        As[a_k + 3][a_mi] = va.w;

        // load B tile
        float4 vb = *(const float4*)(B + (size_t)(k0 + b_kb) * N + n0 + b_n);
        *(float4*)&Bs[b_kb][b_n] = vb;

        __syncthreads();

        #pragma unroll
        for (int kk = 0; kk < BK; kk++) {
            float a[TM], b[TN];
            #pragma unroll
            for (int i = 0; i < TM; i++) a[i] = As[kk][ty * TM + i];
            #pragma unroll
            for (int j = 0; j < TN; j++) b[j] = Bs[kk][tx * TN + j];
            #pragma unroll
            for (int i = 0; i < TM; i++)
                #pragma unroll
                for (int j = 0; j < TN; j++)
                    acc[i][j] = fmaf(a[i], b[j], acc[i][j]);
        }
        __syncthreads();
    }

    // epilogue: bias + optional relu, write (float4 per thread-row)
    const int n = n0 + tx * TN;
    float4 bv = *(const float4*)(bias + n);
    #pragma unroll
    for (int i = 0; i < TM; i++) {
        int m = m0 + ty * TM + i;
        if (m >= count) continue;
        float* crow;
        if (SCATTER_C) crow = C + (size_t)g_tok[m] * ldc;
        else           crow = g_H + (size_t)m * ldc;
        float4 v;
        v.x = acc[i][0] + bv.x;
        v.y = acc[i][1] + bv.y;
        v.z = acc[i][2] + bv.z;
        v.w = acc[i][3] + bv.w;
        if (RELU) {
            v.x = fmaxf(v.x, 0.f);
            v.y = fmaxf(v.y, 0.f);
            v.z = fmaxf(v.z, 0.f);
            v.w = fmaxf(v.w, 0.f);
        }
        *(float4*)(crow + n) = v;
    }
}

// ---------------- launch ----------------
extern "C" void kernel_launch(void* const* d_in, const int* in_sizes, int n_in,
                              void* d_out, int out_size) {
    const int*   ids = (const int*)  d_in[0];
    const float* emb = (const float*)d_in[1];
    const float* w1  = (const float*)d_in[2];
    const float* b1  = (const float*)d_in[3];
    const float* w2  = (const float*)d_in[4];
    const float* b2  = (const float*)d_in[5];
    float*       out = (float*)d_out;

    k_reset<<<1, 1>>>();
    k_compact<<<NTOK / 256, 256>>>(ids);
    k_copy<<<NTOK, 256>>>(emb, ids, out);

    // MLP layer 1: H = relu(out[tok] @ W1 + b1)   [count x 6400], K=3200
    // A is gathered from `out` (already holds emb_table[ids[t]] for every position t)
    dim3 g1(HID / BN, NTOK / BM);
    k_gemm<1, 1, 0><<<g1, 256>>>(out, w1, b1, nullptr, HID, DIM, DIM, HID);

    // MLP layer 2: out[tok] = H @ W2 + b2         [count x 3200], K=6400
    dim3 g2(DIM / BN, NTOK / BM);
    k_gemm<0, 0, 1><<<g2, 256>>>(nullptr, w2, b2, out, DIM, HID, HID, DIM);
}

// round 3
// speedup vs baseline: 3.2003x; 3.2003x over previous
#include <cuda_runtime.h>
#include <stdint.h>

#define DIM        3200
#define HID        6400
#define NTOK       16384   // 8 * 2048
#define NEW_START  32000

// GEMM tiling
#define BM 64
#define BN 64
#define BK 16
#define TM 4
#define TN 4

// split-K config
#define SPLITS1    25      // layer1: K=3200 -> 128 k per split (8 BK iters)
#define KCHUNK1    128
#define SPLITS2    40      // layer2: K=6400 -> 160 k per split (10 BK iters)
#define KCHUNK2    160
#define MAXM_FAST  128     // fast split-K path covers rows [0, 128)

// ---------------- scratch (static device globals; no allocation) ----------------
__device__ int   g_count;
__device__ int   g_tok[NTOK];
__device__ float g_H[(size_t)NTOK * HID];                       // hidden activations
__device__ float g_P[(size_t)SPLITS1 * MAXM_FAST * HID];        // split-K partials (82MB, reused)

// ---------------- kernel 0: reset counter ----------------
__global__ void k_reset() { g_count = 0; }

// ---------------- kernel 1: compact masked token indices ----------------
__global__ void k_compact(const int* __restrict__ ids) {
    int t = blockIdx.x * blockDim.x + threadIdx.x;
    if (t < NTOK && ids[t] >= NEW_START) {
        int p = atomicAdd(&g_count, 1);
        g_tok[p] = t;
    }
}

// ---------------- kernel 2: embedding copy (all tokens) ----------------
__global__ void k_copy(const float* __restrict__ emb,
                       const int*   __restrict__ ids,
                       float*       __restrict__ out) {
    int t = blockIdx.x;
    const float4* src = (const float4*)(emb + (size_t)ids[t] * DIM);
    float4*       dst = (float4*)(out + (size_t)t * DIM);
    #pragma unroll 4
    for (int i = threadIdx.x; i < DIM / 4; i += blockDim.x)
        dst[i] = src[i];
}

// ---------------- split-K GEMM partial kernel ----------------
// blockIdx.x = n-tile, blockIdx.y = k-split, blockIdx.z = m-tile (rows < MAXM_FAST)
// Writes partial sums (no bias/act) to g_P[ (y*MAXM_FAST + m) * N + n ].
// GATHER_A=1: A row m = A + g_tok[m]*lda (gathered embeddings in `out`)
// GATHER_A=0: A row m = g_H + m*lda
template<int GATHER_A>
__global__ void k_gemm_split(const float* __restrict__ A,
                             const float* __restrict__ B,   // weights [K, N] row-major
                             int N, int kchunk, int lda) {
    __shared__ float As[BK][BM + 1];
    __shared__ float Bs[BK][BN];

    const int count = g_count;
    const int m0 = blockIdx.z * BM;
    if (m0 >= count) return;
    const int n0 = blockIdx.x * BN;
    const int kbase = blockIdx.y * kchunk;

    const int tid = threadIdx.x;   // 256
    const int tx = tid & 15;
    const int ty = tid >> 4;

    const int a_mi = tid >> 2;
    const int a_k  = (tid & 3) * 4;
    const int a_m  = m0 + a_mi;
    const float* arow = nullptr;
    if (a_m < count) {
        if (GATHER_A) arow = A + (size_t)g_tok[a_m] * lda;
        else          arow = g_H + (size_t)a_m * lda;
    }

    const int b_kb = tid >> 4;
    const int b_n  = (tid & 15) * 4;

    float acc[TM][TN];
    #pragma unroll
    for (int i = 0; i < TM; i++)
        #pragma unroll
        for (int j = 0; j < TN; j++) acc[i][j] = 0.0f;

    for (int k0 = kbase; k0 < kbase + kchunk; k0 += BK) {
        float4 va = make_float4(0.f, 0.f, 0.f, 0.f);
        if (arow) va = *(const float4*)(arow + k0 + a_k);
        As[a_k + 0][a_mi] = va.x;
        As[a_k + 1][a_mi] = va.y;
        As[a_k + 2][a_mi] = va.z;
        As[a_k + 3][a_mi] = va.w;

        float4 vb = *(const float4*)(B + (size_t)(k0 + b_kb) * N + n0 + b_n);
        *(float4*)&Bs[b_kb][b_n] = vb;

        __syncthreads();

        #pragma unroll
        for (int kk = 0; kk < BK; kk++) {
            float a[TM], b[TN];
            #pragma unroll
            for (int i = 0; i < TM; i++) a[i] = As[kk][ty * TM + i];
            #pragma unroll
            for (int j = 0; j < TN; j++) b[j] = Bs[kk][tx * TN + j];
            #pragma unroll
            for (int i = 0; i < TM; i++)
                #pragma unroll
                for (int j = 0; j < TN; j++)
                    acc[i][j] = fmaf(a[i], b[j], acc[i][j]);
        }
        __syncthreads();
    }

    // write partials (unique writer per (split, m, n) -> deterministic)
    const int n = n0 + tx * TN;
    float* prow_base = g_P + (size_t)blockIdx.y * MAXM_FAST * N;
    #pragma unroll
    for (int i = 0; i < TM; i++) {
        int m = m0 + ty * TM + i;
        if (m >= count) continue;
        float4 v = make_float4(acc[i][0], acc[i][1], acc[i][2], acc[i][3]);
        *(float4*)(prow_base + (size_t)m * N + n) = v;
    }
}

// ---------------- finalize: reduce splits + bias (+relu) + write ----------------
// grid: (ceil(N/256), MAXM_FAST), block 256
__global__ void k_fin(const float* __restrict__ bias,
                      float*       __restrict__ dst,    // used when scatter==1
                      int N, int splits, int relu, int scatter, int ldc) {
    const int n = blockIdx.x * 256 + threadIdx.x;
    const int m = blockIdx.y;
    const int count = g_count;
    if (n >= N || m >= count) return;
    float s = bias[n];
    for (int i = 0; i < splits; i++)
        s += g_P[((size_t)i * MAXM_FAST + m) * N + n];
    if (relu) s = fmaxf(s, 0.f);
    if (scatter) dst[(size_t)g_tok[m] * ldc + n] = s;
    else         g_H[(size_t)m * ldc + n] = s;
}

// ---------------- fallback full-K GEMM (rows >= MAXM_FAST; early-exits normally) --
template<int RELU, int GATHER_A, int SCATTER_C>
__global__ void k_gemm(const float* __restrict__ A,
                       const float* __restrict__ B,
                       const float* __restrict__ bias,
                       float*       __restrict__ C,
                       int N, int K, int lda, int ldc) {
    __shared__ float As[BK][BM + 1];
    __shared__ float Bs[BK][BN];

    const int count = g_count;
    const int m0 = MAXM_FAST + blockIdx.y * BM;
    if (m0 >= count) return;
    const int n0 = blockIdx.x * BN;

    const int tid = threadIdx.x;
    const int tx = tid & 15;
    const int ty = tid >> 4;

    const int a_mi = tid >> 2;
    const int a_k  = (tid & 3) * 4;
    const int a_m  = m0 + a_mi;
    const float* arow = nullptr;
    if (a_m < count) {
        if (GATHER_A) arow = A + (size_t)g_tok[a_m] * lda;
        else          arow = g_H + (size_t)a_m * lda;
    }

    const int b_kb = tid >> 4;
    const int b_n  = (tid & 15) * 4;

    float acc[TM][TN];
    #pragma unroll
    for (int i = 0; i < TM; i++)
        #pragma unroll
        for (int j = 0; j < TN; j++) acc[i][j] = 0.0f;

    for (int k0 = 0; k0 < K; k0 += BK) {
        float4 va = make_float4(0.f, 0.f, 0.f, 0.f);
        if (arow) va = *(const float4*)(arow + k0 + a_k);
        As[a_k + 0][a_mi] = va.x;
        As[a_k + 1][a_mi] = va.y;
        As[a_k + 2][a_mi] = va.z;
        As[a_k + 3][a_mi] = va.w;

        float4 vb = *(const float4*)(B + (size_t)(k0 + b_kb) * N + n0 + b_n);
        *(float4*)&Bs[b_kb][b_n] = vb;

        __syncthreads();

        #pragma unroll
        for (int kk = 0; kk < BK; kk++) {
            float a[TM], b[TN];
            #pragma unroll
            for (int i = 0; i < TM; i++) a[i] = As[kk][ty * TM + i];
            #pragma unroll
            for (int j = 0; j < TN; j++) b[j] = Bs[kk][tx * TN + j];
            #pragma unroll
            for (int i = 0; i < TM; i++)
                #pragma unroll
                for (int j = 0; j < TN; j++)
                    acc[i][j] = fmaf(a[i], b[j], acc[i][j]);
        }
        __syncthreads();
    }

    const int n = n0 + tx * TN;
    float4 bv = *(const float4*)(bias + n);
    #pragma unroll
    for (int i = 0; i < TM; i++) {
        int m = m0 + ty * TM + i;
        if (m >= count) continue;
        float* crow;
        if (SCATTER_C) crow = C + (size_t)g_tok[m] * ldc;
        else           crow = g_H + (size_t)m * ldc;
        float4 v;
        v.x = acc[i][0] + bv.x;
        v.y = acc[i][1] + bv.y;
        v.z = acc[i][2] + bv.z;
        v.w = acc[i][3] + bv.w;
        if (RELU) {
            v.x = fmaxf(v.x, 0.f);
            v.y = fmaxf(v.y, 0.f);
            v.z = fmaxf(v.z, 0.f);
            v.w = fmaxf(v.w, 0.f);
        }
        *(float4*)(crow + n) = v;
    }
}

// ---------------- launch ----------------
extern "C" void kernel_launch(void* const* d_in, const int* in_sizes, int n_in,
                              void* d_out, int out_size) {
    const int*   ids = (const int*)  d_in[0];
    const float* emb = (const float*)d_in[1];
    const float* w1  = (const float*)d_in[2];
    const float* b1  = (const float*)d_in[3];
    const float* w2  = (const float*)d_in[4];
    const float* b2  = (const float*)d_in[5];
    float*       out = (float*)d_out;

    k_reset<<<1, 1>>>();
    k_compact<<<NTOK / 256, 256>>>(ids);
    k_copy<<<NTOK, 256>>>(emb, ids, out);

    // ===== layer 1: H = relu(out[tok] @ W1 + b1), K=3200 =====
    {
        dim3 gs(HID / BN, SPLITS1, MAXM_FAST / BM);
        k_gemm_split<1><<<gs, 256>>>(out, w1, HID, KCHUNK1, DIM);
        dim3 gf((HID + 255) / 256, MAXM_FAST);
        k_fin<<<gf, 256>>>(b1, nullptr, HID, SPLITS1, 1, 0, HID);
        // fallback for rows >= 128 (early-exits when count <= 128)
        dim3 gb(HID / BN, (NTOK - MAXM_FAST) / BM);
        k_gemm<1, 1, 0><<<gb, 256>>>(out, w1, b1, nullptr, HID, DIM, DIM, HID);
    }

    // ===== layer 2: out[tok] = H @ W2 + b2, K=6400 =====
    {
        dim3 gs(DIM / BN, SPLITS2, MAXM_FAST / BM);
        k_gemm_split<0><<<gs, 256>>>(nullptr, w2, DIM, KCHUNK2, HID);
        dim3 gf((DIM + 255) / 256, MAXM_FAST);
        k_fin<<<gf, 256>>>(b2, out, DIM, SPLITS2, 0, 1, DIM);
        dim3 gb(DIM / BN, (NTOK - MAXM_FAST) / BM);
        k_gemm<0, 0, 1><<<gb, 256>>>(nullptr, w2, b2, out, DIM, HID, HID, DIM);
    }
}